// round 8
// baseline (speedup 1.0000x reference)
#include <cuda_runtime.h>
#include <cstdint>
#include <math.h>

#define Bc 2
#define Nc 2048
#define Dc 1024
#define Hc 16
#define E3 192   // 3*DH; chunk order k(0:64), q(64:128), v(128:192)

__device__ float g_kqv[Bc * Hc * Nc * E3];   // [b,h,n,192] (tf32-rounded)
__device__ float g_sa[Bc * Nc * Dc];         // [b,n,d]    (tf32-rounded)
__device__ float g_WkT[Hc * E3 * Dc];        // W_kqv as [c][k], tf32-rounded
__device__ float g_x32[Bc * Nc * Dc];        // x, tf32-rounded
__device__ float g_Wp32[Dc * Dc];            // W_proj, tf32-rounded

__device__ __forceinline__ uint32_t smem_to_u32(const void* p) {
    uint32_t a;
    asm("{ .reg .u64 t; cvta.to.shared.u64 t, %1; cvt.u32.u64 %0, t; }"
        : "=r"(a) : "l"(p));
    return a;
}
__device__ __forceinline__ float to_tf32(float v) {
    float r;
    asm("cvt.rna.tf32.f32 %0, %1;" : "=f"(r) : "f"(v));
    return r;
}
__device__ __forceinline__ void mma_tf32(float* c, const uint32_t* a, const uint32_t* b) {
    asm volatile(
        "mma.sync.aligned.m16n8k8.row.col.f32.tf32.tf32.f32 "
        "{%0,%1,%2,%3}, {%4,%5,%6,%7}, {%8,%9}, {%0,%1,%2,%3};"
        : "+f"(c[0]), "+f"(c[1]), "+f"(c[2]), "+f"(c[3])
        : "r"(a[0]), "r"(a[1]), "r"(a[2]), "r"(a[3]), "r"(b[0]), "r"(b[1]));
}
#define CP16(dst_u32, src_ptr) \
    asm volatile("cp.async.cg.shared.global [%0], [%1], 16;" \
        :: "r"(dst_u32), "l"(src_ptr))
#define CP_COMMIT() asm volatile("cp.async.commit_group;" ::: "memory")
#define CP_WAIT(n)  asm volatile("cp.async.wait_group " #n ";" ::: "memory")

// ---------------------------------------------------------------------------
// Pre-passes: round inputs to tf32 once.
// ---------------------------------------------------------------------------
__global__ __launch_bounds__(256) void round_x(const float* __restrict__ x)
{
    const int i = (blockIdx.x * 256 + threadIdx.x) * 4;
    float4 v = *(const float4*)&x[i];
    v.x = to_tf32(v.x); v.y = to_tf32(v.y); v.z = to_tf32(v.z); v.w = to_tf32(v.w);
    *(float4*)&g_x32[i] = v;
}
__global__ __launch_bounds__(256) void round_wp(const float* __restrict__ Wp)
{
    const int i = (blockIdx.x * 256 + threadIdx.x) * 4;
    float4 v = *(const float4*)&Wp[i];
    v.x = to_tf32(v.x); v.y = to_tf32(v.y); v.z = to_tf32(v.z); v.w = to_tf32(v.w);
    *(float4*)&g_Wp32[i] = v;
}
// Transpose W_kqv [H][D][E3] -> g_WkT [H*E3][D], tf32-rounded.
__global__ __launch_bounds__(256) void transpose_wk(const float* __restrict__ Wk)
{
    __shared__ float tile[32][33];
    const int e0 = blockIdx.x * 32, k0 = blockIdx.y * 32, h = blockIdx.z;
    const float* src = Wk + (size_t)h * Dc * E3;
    float* dst = g_WkT + (size_t)h * E3 * Dc;
    const int tx = threadIdx.x & 31, ty0 = threadIdx.x >> 5;
    #pragma unroll
    for (int i = 0; i < 4; i++) {
        int ty = ty0 + i * 8;
        tile[ty][tx] = src[(size_t)(k0 + ty) * E3 + e0 + tx];
    }
    __syncthreads();
    #pragma unroll
    for (int i = 0; i < 4; i++) {
        int ty = ty0 + i * 8;
        dst[(size_t)(e0 + ty) * Dc + k0 + tx] = to_tf32(tile[tx][ty]);
    }
}

// ---------------------------------------------------------------------------
// tf32 mma.sync GEMM, 3-stage cp.async pipeline. 128x128 CTA tile, 8 warps.
// Inputs pre-rounded to tf32. Dynamic smem: 3 stages x (A 128x36 + B 128x36).
// KQV=true : A=g_x32, B=g_WkT, out->g_kqv (tf32-rounded)
// KQV=false: A=g_sa,  B=g_Wp32, out row-major fp32
// ---------------------------------------------------------------------------
#define SMP 36
#define GSTAGE 9216           // floats per stage (A 4608 + B 4608)
#define GSMEM  (3 * GSTAGE * 4)
template<bool KQV>
__global__ __launch_bounds__(256) void gemm_mma(
    const float* __restrict__ bias, float* __restrict__ outp)
{
    const float* __restrict__ A    = KQV ? (const float*)g_x32 : (const float*)g_sa;
    const float* __restrict__ Bmat = KQV ? (const float*)g_WkT : (const float*)g_Wp32;

    extern __shared__ float sm[];
    const uint32_t su = smem_to_u32(sm);
    const int t = threadIdx.x;
    const int lane = t & 31;
    const int warp = t >> 5;
    const int mbase = (warp >> 2) * 64;
    const int nbase = (warp & 3) * 32;
    const int grp = lane >> 2;
    const int ctg = lane & 3;
    const int c0 = blockIdx.x * 128;
    const int r0 = blockIdx.y * 128;
    const int ld_row = t >> 3;       // 0..31
    const int ld_kq  = (t & 7) * 4;  // 0..28

    auto issue_slab = [&](int s, int buf) {
        const int k0 = s * 32;
        #pragma unroll
        for (int it = 0; it < 4; it++) {
            const int row = it * 32 + ld_row;
            const uint32_t da = su + (uint32_t)(buf * GSTAGE + row * SMP + ld_kq) * 4;
            CP16(da, &A[(size_t)(r0 + row) * Dc + k0 + ld_kq]);
            const uint32_t db = su + (uint32_t)(buf * GSTAGE + 4608 + row * SMP + ld_kq) * 4;
            CP16(db, &Bmat[(size_t)(c0 + row) * Dc + k0 + ld_kq]);
        }
    };

    issue_slab(0, 0); CP_COMMIT();
    issue_slab(1, 1); CP_COMMIT();
    issue_slab(2, 2); CP_COMMIT();

    float C[4][4][4];
    #pragma unroll
    for (int i = 0; i < 4; i++)
        #pragma unroll
        for (int j = 0; j < 4; j++)
            #pragma unroll
            for (int k = 0; k < 4; k++) C[i][j][k] = 0.f;

    for (int s = 0; s < 32; s++) {
        CP_WAIT(2);
        __syncthreads();
        const int buf = s % 3;
        const float* As = sm + buf * GSTAGE;
        const float* Bs = As + 4608;
        #pragma unroll
        for (int kk = 0; kk < 4; kk++) {
            uint32_t af[4][4], bf[4][2];
            const int kof = kk * 8 + ctg;
            #pragma unroll
            for (int tm = 0; tm < 4; tm++) {
                const int m = mbase + tm * 16 + grp;
                af[tm][0] = __float_as_uint(As[m * SMP + kof]);
                af[tm][1] = __float_as_uint(As[(m + 8) * SMP + kof]);
                af[tm][2] = __float_as_uint(As[m * SMP + kof + 4]);
                af[tm][3] = __float_as_uint(As[(m + 8) * SMP + kof + 4]);
            }
            #pragma unroll
            for (int tn = 0; tn < 4; tn++) {
                const int n = nbase + tn * 8 + grp;
                bf[tn][0] = __float_as_uint(Bs[n * SMP + kof]);
                bf[tn][1] = __float_as_uint(Bs[n * SMP + kof + 4]);
            }
            #pragma unroll
            for (int tm = 0; tm < 4; tm++)
                #pragma unroll
                for (int tn = 0; tn < 4; tn++)
                    mma_tf32(C[tm][tn], af[tm], bf[tn]);
        }
        __syncthreads();
        if (s + 3 < 32) issue_slab(s + 3, (s + 3) % 3);
        CP_COMMIT();
    }

    #pragma unroll
    for (int tm = 0; tm < 4; tm++) {
        #pragma unroll
        for (int tn = 0; tn < 4; tn++) {
            const int c = c0 + nbase + tn * 8 + ctg * 2;
            const float bs0 = bias[c], bs1 = bias[c + 1];
            #pragma unroll
            for (int half = 0; half < 2; half++) {
                const int row = r0 + mbase + tm * 16 + grp + half * 8;
                float2 o;
                o.x = C[tm][tn][half * 2 + 0] + bs0;
                o.y = C[tm][tn][half * 2 + 1] + bs1;
                if (KQV) {
                    o.x = to_tf32(o.x); o.y = to_tf32(o.y);
                    const int h = c / E3;
                    const int e = c - h * E3;
                    const int b = row >> 11, n = row & 2047;
                    *(float2*)&g_kqv[(((size_t)(b * Hc + h)) * Nc + n) * E3 + e] = o;
                } else {
                    *(float2*)&outp[(size_t)row * Dc + c] = o;
                }
            }
        }
    }
}

// ---------------------------------------------------------------------------
// Attention: flash, 128-row q-tile, 8 warps x 16 rows, 64-key tiles.
// 2-stage cp.async K/V pipeline (inputs pre-rounded tf32).
// Smem: Ks[2][64][68] @0, Vs[2][64][72] @8704, QPs[128][68] @17920 = 106496B.
// ---------------------------------------------------------------------------
#define ATTN_SMEM 106496
__global__ __launch_bounds__(256) void attn_mma()
{
    extern __shared__ float sm[];
    const uint32_t su = smem_to_u32(sm);
    float* QPs = sm + 17920;   // stride 68

    const int t = threadIdx.x;
    const int lane = t & 31, warp = t >> 5;
    const int grp = lane >> 2, ctg = lane & 3;
    const int mb = warp * 16;
    const int bh = blockIdx.y;
    const int b = bh >> 4, h = bh & 15;
    const int qt = (int)gridDim.x - 1 - (int)blockIdx.x;   // heavy blocks first
    const int q0 = qt * 128;
    const int ntiles = 2 * qt + 2;
    const float* base = g_kqv + (size_t)bh * Nc * E3;

    auto issue_tile = [&](int kt, int bi) {
        const int k0 = kt * 64;
        #pragma unroll
        for (int it = 0; it < 4; it++) {
            const int task = it * 256 + t;
            const int c = task >> 4, d4 = (task & 15) * 4;
            const uint32_t dk = su + (uint32_t)(bi * 4352 + c * 68 + d4) * 4;
            CP16(dk, &base[(size_t)(k0 + c) * E3 + d4]);
            const uint32_t dv = su + (uint32_t)(8704 + bi * 4608 + c * 72 + d4) * 4;
            CP16(dv, &base[(size_t)(k0 + c) * E3 + 128 + d4]);
        }
    };

    issue_tile(0, 0); CP_COMMIT();
    issue_tile(1, 1); CP_COMMIT();

    // stage Q (pre-rounded tf32; x0.125 is exact), build A-fragments
    #pragma unroll
    for (int it = 0; it < 8; it++) {
        const int task = it * 256 + t;
        const int c = task >> 4, d4 = (task & 15) * 4;
        float4 v = *(const float4*)&base[(size_t)(q0 + c) * E3 + 64 + d4];
        v.x *= 0.125f; v.y *= 0.125f; v.z *= 0.125f; v.w *= 0.125f;
        *(float4*)&QPs[c * 68 + d4] = v;
    }
    __syncthreads();
    uint32_t qf[8][4];
    #pragma unroll
    for (int kk = 0; kk < 8; kk++) {
        qf[kk][0] = __float_as_uint(QPs[(mb + grp) * 68 + kk * 8 + ctg]);
        qf[kk][1] = __float_as_uint(QPs[(mb + grp + 8) * 68 + kk * 8 + ctg]);
        qf[kk][2] = __float_as_uint(QPs[(mb + grp) * 68 + kk * 8 + ctg + 4]);
        qf[kk][3] = __float_as_uint(QPs[(mb + grp + 8) * 68 + kk * 8 + ctg + 4]);
    }

    float OC[8][4];
    #pragma unroll
    for (int i = 0; i < 8; i++)
        #pragma unroll
        for (int j = 0; j < 4; j++) OC[i][j] = 0.f;
    float m0 = -1e30f, m1 = -1e30f, l0 = 0.f, l1 = 0.f;
    const int gr0 = q0 + mb + grp, gr1 = gr0 + 8;

    for (int kt = 0; kt < ntiles; kt++) {
        CP_WAIT(1);
        __syncthreads();
        const float* Ksb = sm + (kt & 1) * 4352;            // stride 68
        const float* Vsb = sm + 8704 + (kt & 1) * 4608;     // stride 72

        // ---- S = Q K^T ----
        float SC[8][4];
        #pragma unroll
        for (int i = 0; i < 8; i++)
            #pragma unroll
            for (int j = 0; j < 4; j++) SC[i][j] = 0.f;
        #pragma unroll
        for (int kk = 0; kk < 8; kk++) {
            #pragma unroll
            for (int nt = 0; nt < 8; nt++) {
                uint32_t bf[2];
                bf[0] = __float_as_uint(Ksb[(nt * 8 + grp) * 68 + kk * 8 + ctg]);
                bf[1] = __float_as_uint(Ksb[(nt * 8 + grp) * 68 + kk * 8 + ctg + 4]);
                mma_tf32(SC[nt], qf[kk], bf);
            }
        }

        // ---- causal mask (only last two k-tiles can clip) ----
        if (kt >= 2 * qt) {
            const int kc = kt * 64;
            #pragma unroll
            for (int nt = 0; nt < 8; nt++) {
                const int col = kc + nt * 8 + 2 * ctg;
                if (col > gr0)     SC[nt][0] = -1e30f;
                if (col + 1 > gr0) SC[nt][1] = -1e30f;
                if (col > gr1)     SC[nt][2] = -1e30f;
                if (col + 1 > gr1) SC[nt][3] = -1e30f;
            }
        }

        // ---- online softmax (rows gr0, gr1; reduce over 4 ctg lanes) ----
        float tm0 = -1e30f, tm1 = -1e30f;
        #pragma unroll
        for (int nt = 0; nt < 8; nt++) {
            tm0 = fmaxf(tm0, fmaxf(SC[nt][0], SC[nt][1]));
            tm1 = fmaxf(tm1, fmaxf(SC[nt][2], SC[nt][3]));
        }
        tm0 = fmaxf(tm0, __shfl_xor_sync(0xffffffffu, tm0, 1));
        tm0 = fmaxf(tm0, __shfl_xor_sync(0xffffffffu, tm0, 2));
        tm1 = fmaxf(tm1, __shfl_xor_sync(0xffffffffu, tm1, 1));
        tm1 = fmaxf(tm1, __shfl_xor_sync(0xffffffffu, tm1, 2));
        const float mn0 = fmaxf(m0, tm0), mn1 = fmaxf(m1, tm1);
        const float corr0 = __expf(m0 - mn0), corr1 = __expf(m1 - mn1);
        m0 = mn0; m1 = mn1;
        float s0 = 0.f, s1 = 0.f;
        #pragma unroll
        for (int nt = 0; nt < 8; nt++) {
            SC[nt][0] = __expf(SC[nt][0] - mn0); s0 += SC[nt][0];
            SC[nt][1] = __expf(SC[nt][1] - mn0); s0 += SC[nt][1];
            SC[nt][2] = __expf(SC[nt][2] - mn1); s1 += SC[nt][2];
            SC[nt][3] = __expf(SC[nt][3] - mn1); s1 += SC[nt][3];
        }
        s0 += __shfl_xor_sync(0xffffffffu, s0, 1);
        s0 += __shfl_xor_sync(0xffffffffu, s0, 2);
        s1 += __shfl_xor_sync(0xffffffffu, s1, 1);
        s1 += __shfl_xor_sync(0xffffffffu, s1, 2);
        l0 = l0 * corr0 + s0;
        l1 = l1 * corr1 + s1;
        #pragma unroll
        for (int nt = 0; nt < 8; nt++) {
            OC[nt][0] *= corr0; OC[nt][1] *= corr0;
            OC[nt][2] *= corr1; OC[nt][3] *= corr1;
        }

        // ---- P -> warp-private band of QPs (tf32) ----
        #pragma unroll
        for (int nt = 0; nt < 8; nt++) {
            float2 p0, p1;
            p0.x = to_tf32(SC[nt][0]); p0.y = to_tf32(SC[nt][1]);
            p1.x = to_tf32(SC[nt][2]); p1.y = to_tf32(SC[nt][3]);
            *(float2*)&QPs[(mb + grp) * 68 + nt * 8 + 2 * ctg] = p0;
            *(float2*)&QPs[(mb + grp + 8) * 68 + nt * 8 + 2 * ctg] = p1;
        }
        __syncwarp();

        // ---- O += P V ----
        #pragma unroll
        for (int kk = 0; kk < 8; kk++) {
            uint32_t af[4];
            af[0] = __float_as_uint(QPs[(mb + grp) * 68 + kk * 8 + ctg]);
            af[1] = __float_as_uint(QPs[(mb + grp + 8) * 68 + kk * 8 + ctg]);
            af[2] = __float_as_uint(QPs[(mb + grp) * 68 + kk * 8 + ctg + 4]);
            af[3] = __float_as_uint(QPs[(mb + grp + 8) * 68 + kk * 8 + ctg + 4]);
            #pragma unroll
            for (int dt = 0; dt < 8; dt++) {
                uint32_t bf[2];
                bf[0] = __float_as_uint(Vsb[(kk * 8 + ctg) * 72 + dt * 8 + grp]);
                bf[1] = __float_as_uint(Vsb[(kk * 8 + ctg + 4) * 72 + dt * 8 + grp]);
                mma_tf32(OC[dt], af, bf);
            }
        }
        __syncthreads();
        const int nx = kt + 2;
        if (nx < ntiles) issue_tile(nx, kt & 1);
        CP_COMMIT();
    }

    // ---- epilogue: O / l -> g_sa (tf32-rounded for proj's cp.async path) ----
    const float inv0 = 1.f / l0, inv1 = 1.f / l1;
    const int r0g = b * Nc + q0 + mb + grp;
    #pragma unroll
    for (int dt = 0; dt < 8; dt++) {
        const int c = h * 64 + dt * 8 + 2 * ctg;
        float2 o0, o1;
        o0.x = to_tf32(OC[dt][0] * inv0); o0.y = to_tf32(OC[dt][1] * inv0);
        o1.x = to_tf32(OC[dt][2] * inv1); o1.y = to_tf32(OC[dt][3] * inv1);
        *(float2*)&g_sa[(size_t)r0g * Dc + c] = o0;
        *(float2*)&g_sa[(size_t)(r0g + 8) * Dc + c] = o1;
    }
}

extern "C" void kernel_launch(void* const* d_in, const int* in_sizes, int n_in,
                              void* d_out, int out_size)
{
    const float* x  = (const float*)d_in[0];
    const float* Wk = (const float*)d_in[1];
    const float* bk = (const float*)d_in[2];
    const float* Wp = (const float*)d_in[3];
    const float* bp = (const float*)d_in[4];
    float* out = (float*)d_out;

    cudaFuncSetAttribute((const void*)gemm_mma<true>,
                         cudaFuncAttributeMaxDynamicSharedMemorySize, GSMEM);
    cudaFuncSetAttribute((const void*)gemm_mma<false>,
                         cudaFuncAttributeMaxDynamicSharedMemorySize, GSMEM);
    cudaFuncSetAttribute((const void*)attn_mma,
                         cudaFuncAttributeMaxDynamicSharedMemorySize, ATTN_SMEM);

    round_x<<<4096, 256>>>(x);
    round_wp<<<1024, 256>>>(Wp);
    transpose_wk<<<dim3(6, 32, 16), 256>>>(Wk);

    gemm_mma<true><<<dim3(24, 32), 256, GSMEM>>>(bk, nullptr);

    attn_mma<<<dim3(16, 32), 256, ATTN_SMEM>>>();

    gemm_mma<false><<<dim3(8, 32), 256, GSMEM>>>(bp, out);
}

// round 10
// speedup vs baseline: 1.6010x; 1.6010x over previous
#include <cuda_runtime.h>
#include <cstdint>
#include <math.h>

#define Bc 2
#define Nc 2048
#define Dc 1024
#define Hc 16
#define E3 192   // 3*DH; chunk order k(0:64), q(64:128), v(128:192)

__device__ float g_kqv[Bc * Hc * Nc * E3];   // [b,h,n,192] (tf32-rounded)
__device__ float g_sa[Bc * Nc * Dc];         // [b,n,d]    (tf32-rounded)
__device__ float g_WkT[Hc * E3 * Dc];        // W_kqv as [c][k], tf32-rounded
__device__ float g_x32[Bc * Nc * Dc];        // x, tf32-rounded
__device__ float g_Wp32[Dc * Dc];            // W_proj, tf32-rounded

__device__ __forceinline__ uint32_t smem_to_u32(const void* p) {
    uint32_t a;
    asm("{ .reg .u64 t; cvta.to.shared.u64 t, %1; cvt.u32.u64 %0, t; }"
        : "=r"(a) : "l"(p));
    return a;
}
__device__ __forceinline__ float to_tf32(float v) {
    float r;
    asm("cvt.rna.tf32.f32 %0, %1;" : "=f"(r) : "f"(v));
    return r;
}
__device__ __forceinline__ float4 to_tf32_4(float4 v) {
    float4 r;
    r.x = to_tf32(v.x); r.y = to_tf32(v.y); r.z = to_tf32(v.z); r.w = to_tf32(v.w);
    return r;
}
__device__ __forceinline__ void mma_tf32(float* c, const uint32_t* a, const uint32_t* b) {
    asm volatile(
        "mma.sync.aligned.m16n8k8.row.col.f32.tf32.tf32.f32 "
        "{%0,%1,%2,%3}, {%4,%5,%6,%7}, {%8,%9}, {%0,%1,%2,%3};"
        : "+f"(c[0]), "+f"(c[1]), "+f"(c[2]), "+f"(c[3])
        : "r"(a[0]), "r"(a[1]), "r"(a[2]), "r"(a[3]), "r"(b[0]), "r"(b[1]));
}
#define CP16(dst_u32, src_ptr) \
    asm volatile("cp.async.cg.shared.global [%0], [%1], 16;" \
        :: "r"(dst_u32), "l"(src_ptr))
#define CP_COMMIT() asm volatile("cp.async.commit_group;" ::: "memory")
#define CP_WAIT1()  asm volatile("cp.async.wait_group 1;" ::: "memory")
#define CP_WAIT0()  asm volatile("cp.async.wait_group 0;" ::: "memory")

// ---------------------------------------------------------------------------
// Pre-passes: round inputs to tf32 once.
// ---------------------------------------------------------------------------
__global__ __launch_bounds__(256) void round_x(const float* __restrict__ x)
{
    const int i = (blockIdx.x * 256 + threadIdx.x) * 4;
    float4 v = *(const float4*)&x[i];
    *(float4*)&g_x32[i] = to_tf32_4(v);
}
__global__ __launch_bounds__(256) void round_wp(const float* __restrict__ Wp)
{
    const int i = (blockIdx.x * 256 + threadIdx.x) * 4;
    float4 v = *(const float4*)&Wp[i];
    *(float4*)&g_Wp32[i] = to_tf32_4(v);
}
// Transpose W_kqv [H][D][E3] -> g_WkT [H*E3][D], tf32-rounded.
__global__ __launch_bounds__(256) void transpose_wk(const float* __restrict__ Wk)
{
    __shared__ float tile[32][33];
    const int e0 = blockIdx.x * 32, k0 = blockIdx.y * 32, h = blockIdx.z;
    const float* src = Wk + (size_t)h * Dc * E3;
    float* dst = g_WkT + (size_t)h * E3 * Dc;
    const int tx = threadIdx.x & 31, ty0 = threadIdx.x >> 5;
    #pragma unroll
    for (int i = 0; i < 4; i++) {
        int ty = ty0 + i * 8;
        tile[ty][tx] = src[(size_t)(k0 + ty) * E3 + e0 + tx];
    }
    __syncthreads();
    #pragma unroll
    for (int i = 0; i < 4; i++) {
        int ty = ty0 + i * 8;
        dst[(size_t)(e0 + ty) * Dc + k0 + tx] = to_tf32(tile[tx][ty]);
    }
}

// ---------------------------------------------------------------------------
// tf32 mma.sync GEMM: 128x128 CTA tile, 4 warps (2x2), warp tile 64x64.
// 2-stage cp.async; inputs pre-rounded tf32. Dynamic smem 72KB -> 2 CTA/SM.
// Crossbar per slab ~96KB vs tensor ~1024cyc -> tensor-bound.
// ---------------------------------------------------------------------------
#define GSMP 36
#define GSTG 9216                 // floats per stage (A 4608 + B 4608)
#define GSMEM (2 * GSTG * 4)      // 73728 B
template<bool KQV>
__global__ __launch_bounds__(128) void gemm_mma(
    const float* __restrict__ bias, float* __restrict__ outp)
{
    const float* __restrict__ A    = KQV ? (const float*)g_x32 : (const float*)g_sa;
    const float* __restrict__ Bmat = KQV ? (const float*)g_WkT : (const float*)g_Wp32;

    extern __shared__ float sm[];
    const uint32_t su = smem_to_u32(sm);
    const int t = threadIdx.x;
    const int lane = t & 31;
    const int warp = t >> 5;           // 0..3
    const int mbase = (warp >> 1) * 64;
    const int nbase = (warp & 1) * 64;
    const int grp = lane >> 2;
    const int ctg = lane & 3;
    const int c0 = blockIdx.x * 128;
    const int r0 = blockIdx.y * 128;

    auto issue_slab = [&](int s, int buf) {
        const int k0 = s * 32;
        #pragma unroll
        for (int it = 0; it < 8; it++) {
            const int task = it * 128 + t;
            const int row = task >> 3, i4 = (task & 7) * 4;
            CP16(su + (uint32_t)(buf * GSTG + row * GSMP + i4) * 4,
                 &A[(size_t)(r0 + row) * Dc + k0 + i4]);
            CP16(su + (uint32_t)(buf * GSTG + 4608 + row * GSMP + i4) * 4,
                 &Bmat[(size_t)(c0 + row) * Dc + k0 + i4]);
        }
    };

    issue_slab(0, 0); CP_COMMIT();
    issue_slab(1, 1); CP_COMMIT();

    float C[4][8][4];
    #pragma unroll
    for (int i = 0; i < 4; i++)
        #pragma unroll
        for (int j = 0; j < 8; j++)
            #pragma unroll
            for (int k = 0; k < 4; k++) C[i][j][k] = 0.f;

    for (int s = 0; s < 32; s++) {
        if (s == 31) { CP_WAIT0(); } else { CP_WAIT1(); }
        __syncthreads();
        const float* As = sm + (s & 1) * GSTG;
        const float* Bs = As + 4608;
        #pragma unroll
        for (int kk = 0; kk < 4; kk++) {
            const int kof = kk * 8 + ctg;
            uint32_t af[4][4];
            #pragma unroll
            for (int tm = 0; tm < 4; tm++) {
                const int m = mbase + tm * 16 + grp;
                af[tm][0] = __float_as_uint(As[m * GSMP + kof]);
                af[tm][1] = __float_as_uint(As[(m + 8) * GSMP + kof]);
                af[tm][2] = __float_as_uint(As[m * GSMP + kof + 4]);
                af[tm][3] = __float_as_uint(As[(m + 8) * GSMP + kof + 4]);
            }
            #pragma unroll
            for (int tn = 0; tn < 8; tn++) {
                const int n = nbase + tn * 8 + grp;
                uint32_t bf[2];
                bf[0] = __float_as_uint(Bs[n * GSMP + kof]);
                bf[1] = __float_as_uint(Bs[n * GSMP + kof + 4]);
                #pragma unroll
                for (int tm = 0; tm < 4; tm++)
                    mma_tf32(C[tm][tn], af[tm], bf);
            }
        }
        __syncthreads();
        if (s + 2 < 32) issue_slab(s + 2, s & 1);
        CP_COMMIT();
    }

    // Epilogue: C rows grp/grp+8, cols 2*ctg, 2*ctg+1
    #pragma unroll
    for (int tm = 0; tm < 4; tm++) {
        #pragma unroll
        for (int tn = 0; tn < 8; tn++) {
            const int c = c0 + nbase + tn * 8 + ctg * 2;
            const float bs0 = bias[c], bs1 = bias[c + 1];
            #pragma unroll
            for (int half = 0; half < 2; half++) {
                const int row = r0 + mbase + tm * 16 + grp + half * 8;
                float2 o;
                o.x = C[tm][tn][half * 2 + 0] + bs0;
                o.y = C[tm][tn][half * 2 + 1] + bs1;
                if (KQV) {
                    o.x = to_tf32(o.x); o.y = to_tf32(o.y);
                    const int h = c / E3;
                    const int e = c - h * E3;
                    const int b = row >> 11, n = row & 2047;
                    *(float2*)&g_kqv[(((size_t)(b * Hc + h)) * Nc + n) * E3 + e] = o;
                } else {
                    *(float2*)&outp[(size_t)row * Dc + c] = o;
                }
            }
        }
    }
}

// ---------------------------------------------------------------------------
// Attention (round-7 version, known good): flash, 64x64 tile, 4 warps x 16 rows.
// Epilogue rounds g_sa to tf32 for proj's cp.async path.
// ---------------------------------------------------------------------------
#define ATTN_SMEM 53248
__global__ __launch_bounds__(128) void attn_mma()
{
    extern __shared__ float sm[];
    float* Ks  = sm;           // stride 68
    float* QPs = sm + 4352;    // stride 68 (Q staged, then P per-warp bands)
    float* Vs  = sm + 8704;    // stride 72

    const int t = threadIdx.x;
    const int lane = t & 31, warp = t >> 5;
    const int grp = lane >> 2, ctg = lane & 3;
    const int mb = warp * 16;
    const int bh = blockIdx.y;
    const int b = bh >> 4, h = bh & 15;
    const int qt = (int)gridDim.x - 1 - (int)blockIdx.x;   // heavy blocks first
    const int q0 = qt * 64;
    const float* base = g_kqv + (size_t)bh * Nc * E3;

    #pragma unroll
    for (int it = 0; it < 8; it++) {
        int task = it * 128 + t;
        int c = task >> 4, d4 = (task & 15) * 4;
        float4 v = *(const float4*)&base[(size_t)(q0 + c) * E3 + 64 + d4];
        v.x *= 0.125f; v.y *= 0.125f; v.z *= 0.125f; v.w *= 0.125f;
        *(float4*)&QPs[c * 68 + d4] = v;
    }
    __syncthreads();
    uint32_t qf[8][4];
    #pragma unroll
    for (int kk = 0; kk < 8; kk++) {
        qf[kk][0] = __float_as_uint(QPs[(mb + grp) * 68 + kk * 8 + ctg]);
        qf[kk][1] = __float_as_uint(QPs[(mb + grp + 8) * 68 + kk * 8 + ctg]);
        qf[kk][2] = __float_as_uint(QPs[(mb + grp) * 68 + kk * 8 + ctg + 4]);
        qf[kk][3] = __float_as_uint(QPs[(mb + grp + 8) * 68 + kk * 8 + ctg + 4]);
    }

    float OC[8][4];
    #pragma unroll
    for (int i = 0; i < 8; i++)
        #pragma unroll
        for (int j = 0; j < 4; j++) OC[i][j] = 0.f;
    float m0 = -1e30f, m1 = -1e30f, l0 = 0.f, l1 = 0.f;

    for (int kt = 0; kt <= qt; kt++) {
        const int k0 = kt * 64;
        __syncthreads();
        #pragma unroll
        for (int it = 0; it < 8; it++) {
            int task = it * 128 + t;
            int c = task >> 4, d4 = (task & 15) * 4;
            float4 v = *(const float4*)&base[(size_t)(k0 + c) * E3 + d4];
            *(float4*)&Ks[c * 68 + d4] = v;
        }
        #pragma unroll
        for (int it = 0; it < 8; it++) {
            int task = it * 128 + t;
            int c = task >> 4, d4 = (task & 15) * 4;
            float4 v = *(const float4*)&base[(size_t)(k0 + c) * E3 + 128 + d4];
            *(float4*)&Vs[c * 72 + d4] = v;
        }
        __syncthreads();

        float SC[8][4];
        #pragma unroll
        for (int i = 0; i < 8; i++)
            #pragma unroll
            for (int j = 0; j < 4; j++) SC[i][j] = 0.f;
        #pragma unroll
        for (int kk = 0; kk < 8; kk++) {
            #pragma unroll
            for (int nt = 0; nt < 8; nt++) {
                uint32_t bf[2];
                bf[0] = __float_as_uint(Ks[(nt * 8 + grp) * 68 + kk * 8 + ctg]);
                bf[1] = __float_as_uint(Ks[(nt * 8 + grp) * 68 + kk * 8 + ctg + 4]);
                mma_tf32(SC[nt], qf[kk], bf);
            }
        }

        if (kt == qt) {
            const int r0l = mb + grp, r1l = mb + grp + 8;
            #pragma unroll
            for (int nt = 0; nt < 8; nt++) {
                const int col = nt * 8 + 2 * ctg;
                if (col > r0l)     SC[nt][0] = -1e30f;
                if (col + 1 > r0l) SC[nt][1] = -1e30f;
                if (col > r1l)     SC[nt][2] = -1e30f;
                if (col + 1 > r1l) SC[nt][3] = -1e30f;
            }
        }

        float tm0 = -1e30f, tm1 = -1e30f;
        #pragma unroll
        for (int nt = 0; nt < 8; nt++) {
            tm0 = fmaxf(tm0, fmaxf(SC[nt][0], SC[nt][1]));
            tm1 = fmaxf(tm1, fmaxf(SC[nt][2], SC[nt][3]));
        }
        tm0 = fmaxf(tm0, __shfl_xor_sync(0xffffffffu, tm0, 1));
        tm0 = fmaxf(tm0, __shfl_xor_sync(0xffffffffu, tm0, 2));
        tm1 = fmaxf(tm1, __shfl_xor_sync(0xffffffffu, tm1, 1));
        tm1 = fmaxf(tm1, __shfl_xor_sync(0xffffffffu, tm1, 2));
        const float mn0 = fmaxf(m0, tm0), mn1 = fmaxf(m1, tm1);
        const float corr0 = __expf(m0 - mn0), corr1 = __expf(m1 - mn1);
        m0 = mn0; m1 = mn1;
        float s0 = 0.f, s1 = 0.f;
        #pragma unroll
        for (int nt = 0; nt < 8; nt++) {
            SC[nt][0] = __expf(SC[nt][0] - mn0); s0 += SC[nt][0];
            SC[nt][1] = __expf(SC[nt][1] - mn0); s0 += SC[nt][1];
            SC[nt][2] = __expf(SC[nt][2] - mn1); s1 += SC[nt][2];
            SC[nt][3] = __expf(SC[nt][3] - mn1); s1 += SC[nt][3];
        }
        s0 += __shfl_xor_sync(0xffffffffu, s0, 1);
        s0 += __shfl_xor_sync(0xffffffffu, s0, 2);
        s1 += __shfl_xor_sync(0xffffffffu, s1, 1);
        s1 += __shfl_xor_sync(0xffffffffu, s1, 2);
        l0 = l0 * corr0 + s0;
        l1 = l1 * corr1 + s1;
        #pragma unroll
        for (int nt = 0; nt < 8; nt++) {
            OC[nt][0] *= corr0; OC[nt][1] *= corr0;
            OC[nt][2] *= corr1; OC[nt][3] *= corr1;
        }

        #pragma unroll
        for (int nt = 0; nt < 8; nt++) {
            float2 p0, p1;
            p0.x = to_tf32(SC[nt][0]); p0.y = to_tf32(SC[nt][1]);
            p1.x = to_tf32(SC[nt][2]); p1.y = to_tf32(SC[nt][3]);
            *(float2*)&QPs[(mb + grp) * 68 + nt * 8 + 2 * ctg] = p0;
            *(float2*)&QPs[(mb + grp + 8) * 68 + nt * 8 + 2 * ctg] = p1;
        }
        __syncwarp();

        #pragma unroll
        for (int kk = 0; kk < 8; kk++) {
            uint32_t af[4];
            af[0] = __float_as_uint(QPs[(mb + grp) * 68 + kk * 8 + ctg]);
            af[1] = __float_as_uint(QPs[(mb + grp + 8) * 68 + kk * 8 + ctg]);
            af[2] = __float_as_uint(QPs[(mb + grp) * 68 + kk * 8 + ctg + 4]);
            af[3] = __float_as_uint(QPs[(mb + grp + 8) * 68 + kk * 8 + ctg + 4]);
            #pragma unroll
            for (int dt = 0; dt < 8; dt++) {
                uint32_t bf[2];
                bf[0] = __float_as_uint(Vs[(kk * 8 + ctg) * 72 + dt * 8 + grp]);
                bf[1] = __float_as_uint(Vs[(kk * 8 + ctg + 4) * 72 + dt * 8 + grp]);
                mma_tf32(OC[dt], af, bf);
            }
        }
    }

    const float inv0 = 1.f / l0, inv1 = 1.f / l1;
    const int r0g = b * Nc + q0 + mb + grp;
    #pragma unroll
    for (int dt = 0; dt < 8; dt++) {
        const int c = h * 64 + dt * 8 + 2 * ctg;
        float2 o0, o1;
        o0.x = to_tf32(OC[dt][0] * inv0); o0.y = to_tf32(OC[dt][1] * inv0);
        o1.x = to_tf32(OC[dt][2] * inv1); o1.y = to_tf32(OC[dt][3] * inv1);
        *(float2*)&g_sa[(size_t)r0g * Dc + c] = o0;
        *(float2*)&g_sa[(size_t)(r0g + 8) * Dc + c] = o1;
    }
}

extern "C" void kernel_launch(void* const* d_in, const int* in_sizes, int n_in,
                              void* d_out, int out_size)
{
    const float* x  = (const float*)d_in[0];
    const float* Wk = (const float*)d_in[1];
    const float* bk = (const float*)d_in[2];
    const float* Wp = (const float*)d_in[3];
    const float* bp = (const float*)d_in[4];
    float* out = (float*)d_out;

    cudaFuncSetAttribute((const void*)gemm_mma<true>,
                         cudaFuncAttributeMaxDynamicSharedMemorySize, GSMEM);
    cudaFuncSetAttribute((const void*)gemm_mma<false>,
                         cudaFuncAttributeMaxDynamicSharedMemorySize, GSMEM);
    cudaFuncSetAttribute((const void*)attn_mma,
                         cudaFuncAttributeMaxDynamicSharedMemorySize, ATTN_SMEM);

    round_x<<<4096, 256>>>(x);
    round_wp<<<1024, 256>>>(Wp);
    transpose_wk<<<dim3(6, 32, 16), 256>>>(Wk);

    gemm_mma<true><<<dim3(24, 32), 128, GSMEM>>>(bk, nullptr);

    attn_mma<<<dim3(32, 32), 128, ATTN_SMEM>>>();

    gemm_mma<false><<<dim3(8, 32), 128, GSMEM>>>(bp, out);
}